// round 11
// baseline (speedup 1.0000x reference)
#include <cuda_runtime.h>
#include <math.h>

#define B_   8
#define N_   4096
#define M_   1024
#define K_   32
#define CIN_ 64
#define CT_  64
#define C1_  64
#define C2_  128
#define G_   8

// ---------------- device scratch (no allocations allowed) ----------------
__device__ int   g_nidx[B_ * M_ * K_];          // kNN indices
__device__ float g_z1[B_ * C1_ * M_ * K_];      // pre-GN1 activations (67 MB)
__device__ float g_z2[B_ * C2_ * M_ * K_];      // pre-GN2 activations (134 MB)
__device__ float g_part[B_ * G_ * 16 * 2];      // partial sums (reused both phases)
__device__ float g_ms1[B_ * G_ * 2];            // mean, rstd for GN1
__device__ float g_ms2[B_ * G_ * 2];            // mean, rstd for GN2

// ---------------------------------------------------------------------
// Kernel 1: furthest point sampling. One block per batch, 1024 threads,
// 4 points per thread held in registers. Writes centers directly to out.
// Matches jnp.argmax (first max = lowest index) tie-breaking: dist >= 0 so
// float bits are order-preserving as u32; lane order == index order, so
// ffs(ballot) picks the lowest index among equal maxima.
// ---------------------------------------------------------------------
__global__ void fps_kernel(const float* __restrict__ coords,
                           float* __restrict__ centers) {
    const int b = blockIdx.x;
    const float* cx = coords + (b * 3 + 0) * N_;
    const float* cy = coords + (b * 3 + 1) * N_;
    const float* cz = coords + (b * 3 + 2) * N_;
    const int t  = threadIdx.x;
    const int n0 = t * 4;

    float4 vx = *(const float4*)(cx + n0);
    float4 vy = *(const float4*)(cy + n0);
    float4 vz = *(const float4*)(cz + n0);
    float px[4] = {vx.x, vx.y, vx.z, vx.w};
    float py[4] = {vy.x, vy.y, vy.z, vy.w};
    float pz[4] = {vz.x, vz.y, vz.z, vz.w};

    float fx = cx[0], fy = cy[0], fz = cz[0];
    float dist[4];
#pragma unroll
    for (int j = 0; j < 4; j++) {
        float dx = __fsub_rn(px[j], fx);
        float dy = __fsub_rn(py[j], fy);
        float dz = __fsub_rn(pz[j], fz);
        dist[j] = fmaf(dz, dz, fmaf(dy, dy, __fmul_rn(dx, dx)));
    }
    if (t == 0) {
        centers[(b * 3 + 0) * M_ + 0] = fx;
        centers[(b * 3 + 1) * M_ + 0] = fy;
        centers[(b * 3 + 2) * M_ + 0] = fz;
    }

    __shared__ unsigned swk[32];
    __shared__ int      swn[32];
    __shared__ int      s_far;
    const int lane = t & 31, wid = t >> 5;

    for (int s = 1; s < M_; s++) {
        // local argmax over 4 (strict > keeps the lowest index)
        float bd = dist[0];
        int   bn = n0;
#pragma unroll
        for (int j = 1; j < 4; j++)
            if (dist[j] > bd) { bd = dist[j]; bn = n0 + j; }

        unsigned db   = __float_as_uint(bd);  // dist >= 0: bits monotone
        unsigned wmax = __reduce_max_sync(0xffffffffu, db);
        unsigned msk  = __ballot_sync(0xffffffffu, db == wmax);
        int src = __ffs(msk) - 1;             // lowest lane == lowest index
        int wbn = __shfl_sync(0xffffffffu, bn, src);
        if (lane == 0) { swk[wid] = wmax; swn[wid] = wbn; }
        __syncthreads();
        if (wid == 0) {
            unsigned d2  = swk[lane];
            unsigned m2  = __reduce_max_sync(0xffffffffu, d2);
            unsigned mk2 = __ballot_sync(0xffffffffu, d2 == m2);
            int sw = __ffs(mk2) - 1;          // lowest warp == lowest index
            if (lane == 0) s_far = swn[sw];
        }
        __syncthreads();
        const int far = s_far;
        fx = __ldg(cx + far); fy = __ldg(cy + far); fz = __ldg(cz + far);
        if (t == 0) {
            centers[(b * 3 + 0) * M_ + s] = fx;
            centers[(b * 3 + 1) * M_ + s] = fy;
            centers[(b * 3 + 2) * M_ + s] = fz;
        }
#pragma unroll
        for (int j = 0; j < 4; j++) {
            float dx = __fsub_rn(px[j], fx);
            float dy = __fsub_rn(py[j], fy);
            float dz = __fsub_rn(pz[j], fz);
            float dd = fmaf(dz, dz, fmaf(dy, dy, __fmul_rn(dx, dx)));
            dist[j] = fminf(dist[j], dd);
        }
    }
}

// ---------------------------------------------------------------------
// Kernel 2: kNN (top-K smallest of the reference's d = |c|^2+|p|^2-2c.p).
// One block of 256 threads per (m, b). 64-bit keys (dist-bits<<32 | n)
// reproduce jax top_k's stable tie-breaking as a SET (order is irrelevant
// downstream: everything is max over K). Selection = per-thread min cache
// + 32 serial extractions (only the winner rescans its 16 slots).
// ---------------------------------------------------------------------
__global__ void knn_kernel(const float* __restrict__ coords,
                           const float* __restrict__ centers) {
    const int m = blockIdx.x, b = blockIdx.y, tid = threadIdx.x;
    __shared__ unsigned long long skey[N_];   // 32 KB
    __shared__ unsigned long long scur[256];
    __shared__ unsigned long long s_win;

    const float* cx = coords + (b * 3 + 0) * N_;
    const float* cy = coords + (b * 3 + 1) * N_;
    const float* cz = coords + (b * 3 + 2) * N_;
    const float qx = centers[(b * 3 + 0) * M_ + m];
    const float qy = centers[(b * 3 + 1) * M_ + m];
    const float qz = centers[(b * 3 + 2) * M_ + m];
    const float cn = fmaf(qz, qz, fmaf(qy, qy, __fmul_rn(qx, qx)));

    for (int n = tid; n < N_; n += 256) {
        float x = cx[n], y = cy[n], z = cz[n];
        float pn = fmaf(z, z, fmaf(y, y, __fmul_rn(x, x)));
        float dt = fmaf(qz, z, fmaf(qy, y, __fmul_rn(qx, x)));
        float d  = __fsub_rn(__fadd_rn(cn, pn), __fmul_rn(2.0f, dt));
        unsigned ub = __float_as_uint(d);
        ub = (ub & 0x80000000u) ? ~ub : (ub | 0x80000000u);
        skey[n] = ((unsigned long long)ub << 32) | (unsigned)n;
    }
    {
        unsigned long long best = ~0ull;
#pragma unroll
        for (int j = 0; j < N_ / 256; j++) {
            unsigned long long v = skey[tid + j * 256];
            best = (v < best) ? v : best;
        }
        scur[tid] = best;
    }
    __syncthreads();

    int* outp = g_nidx + (b * M_ + m) * K_;
    for (int r = 0; r < K_; r++) {
        if (tid < 32) {
            unsigned long long mk = scur[tid];
#pragma unroll
            for (int j = 1; j < 8; j++) {
                unsigned long long v = scur[tid + j * 32];
                mk = (v < mk) ? v : mk;
            }
#pragma unroll
            for (int off = 16; off > 0; off >>= 1) {
                unsigned long long v = __shfl_down_sync(0xffffffffu, mk, off);
                mk = (v < mk) ? v : mk;
            }
            if (tid == 0) {
                s_win  = mk;
                outp[r] = (int)(unsigned)mk;   // low 32 bits = n
            }
        }
        __syncthreads();
        unsigned long long wk = s_win;
        if (scur[tid] == wk) {                 // keys unique -> one thread
            unsigned long long best = ~0ull;
#pragma unroll
            for (int j = 0; j < N_ / 256; j++) {
                int pos = tid + j * 256;
                unsigned long long v = skey[pos];
                if (v == wk) { skey[pos] = ~0ull; v = ~0ull; }
                best = (v < best) ? v : best;
            }
            scur[tid] = best;
        }
        __syncthreads();
    }
}

// ---------------------------------------------------------------------
// Kernel 3: gather (rel-coords ++ features) -> z1 = W1 * gfeat + b1.
// Also produces gtemb max (no activation, straight max over K).
// One block of 256 threads per (m, b). W1 (64x67) cached in shared.
// sF stride 67 (odd) -> conflict-free across k lanes.
// ---------------------------------------------------------------------
__global__ void mlp1_kernel(const float* __restrict__ features,
                            const float* __restrict__ coords,
                            const float* __restrict__ temb,
                            const float* __restrict__ W1,
                            const float* __restrict__ b1,
                            const float* __restrict__ centers,
                            float* __restrict__ out_temb) {
    const int m = blockIdx.x, b = blockIdx.y, tid = threadIdx.x;
    __shared__ float sW[C1_ * 67];   // 16.75 KB
    __shared__ float sF[K_ * 67];    // 8.4 KB
    __shared__ int   sN[K_];

    for (int i = tid; i < C1_ * 67; i += 256) sW[i] = W1[i];
    if (tid < K_) sN[tid] = g_nidx[(b * M_ + m) * K_ + tid];
    __syncthreads();

    const float c0 = centers[(b * 3 + 0) * M_ + m];
    const float c1 = centers[(b * 3 + 1) * M_ + m];
    const float c2 = centers[(b * 3 + 2) * M_ + m];

    for (int i = tid; i < K_ * 67; i += 256) {
        int k = i / 67, c = i - k * 67;
        int n = sN[k];
        float v;
        if      (c == 0) v = __fsub_rn(coords[(b * 3 + 0) * N_ + n], c0);
        else if (c == 1) v = __fsub_rn(coords[(b * 3 + 1) * N_ + n], c1);
        else if (c == 2) v = __fsub_rn(coords[(b * 3 + 2) * N_ + n], c2);
        else             v = features[(b * CIN_ + (c - 3)) * N_ + n];
        sF[k * 67 + c] = v;
    }
    __syncthreads();

    const int k  = tid & 31;
    const int ob = (tid >> 5) * 8;
    float acc[8];
#pragma unroll
    for (int o = 0; o < 8; o++) acc[o] = b1[ob + o];
    for (int c = 0; c < 67; c++) {
        float f = sF[k * 67 + c];
#pragma unroll
        for (int o = 0; o < 8; o++)
            acc[o] = fmaf(sW[(ob + o) * 67 + c], f, acc[o]);
    }
#pragma unroll
    for (int o = 0; o < 8; o++)
        g_z1[((b * C1_ + ob + o) * M_ + m) * K_ + k] = acc[o];

    if (tid < CT_) {
        const float* tb = temb + (b * CT_ + tid) * N_;
        float mx = -3.402823466e38f;
#pragma unroll
        for (int kk = 0; kk < K_; kk++) mx = fmaxf(mx, __ldg(tb + sN[kk]));
        out_temb[(b * CT_ + tid) * M_ + m] = mx;
    }
}

// ---------------------------------------------------------------------
// GroupNorm stats, deterministic two-stage (no float atomics).
// PHASE 0: z1 (8 ch/group, split 8). PHASE 1: z2 (16 ch/group, split 16).
// Group channels are contiguous in [B][C][M][K] layout.
// ---------------------------------------------------------------------
template <int PHASE>
__global__ void gn_partial_kernel() {
    const int   split = (PHASE == 0) ? 8 : 16;
    const int   epg   = (PHASE == 0) ? (C1_ / G_) * M_ * K_ : (C2_ / G_) * M_ * K_;
    const float* z    = (PHASE == 0) ? g_z1 : g_z2;
    const int grp = blockIdx.x / split, sp = blockIdx.x % split;
    const int chunk = epg / split;    // 32768
    const float* p = z + (size_t)grp * epg + (size_t)sp * chunk;

    float s = 0.f, sq = 0.f;
    for (int i = threadIdx.x * 4; i < chunk; i += 256 * 4) {
        float4 v = *(const float4*)(p + i);
        s  += v.x + v.y + v.z + v.w;
        sq += v.x * v.x + v.y * v.y + v.z * v.z + v.w * v.w;
    }
    __shared__ float rs[8], rq[8];
#pragma unroll
    for (int off = 16; off > 0; off >>= 1) {
        s  += __shfl_down_sync(0xffffffffu, s, off);
        sq += __shfl_down_sync(0xffffffffu, sq, off);
    }
    const int lane = threadIdx.x & 31, wid = threadIdx.x >> 5;
    if (lane == 0) { rs[wid] = s; rq[wid] = sq; }
    __syncthreads();
    if (threadIdx.x < 8) {
        s = rs[threadIdx.x]; sq = rq[threadIdx.x];
#pragma unroll
        for (int off = 4; off > 0; off >>= 1) {
            s  += __shfl_down_sync(0xffu, s, off);
            sq += __shfl_down_sync(0xffu, sq, off);
        }
        if (threadIdx.x == 0) {
            g_part[blockIdx.x * 2]     = s;
            g_part[blockIdx.x * 2 + 1] = sq;
        }
    }
}

template <int PHASE>
__global__ void gn_finalize_kernel() {
    const int   split = (PHASE == 0) ? 8 : 16;
    const float cnt   = (PHASE == 0) ? 262144.f : 524288.f;
    float* ms = (PHASE == 0) ? g_ms1 : g_ms2;
    const int g = threadIdx.x;  // 64 = B*G
    float s = 0.f, sq = 0.f;
    for (int i = 0; i < split; i++) {
        s  += g_part[(g * split + i) * 2];
        sq += g_part[(g * split + i) * 2 + 1];
    }
    float mean = s / cnt;
    float var  = fmaxf(sq / cnt - mean * mean, 0.f);
    ms[g * 2]     = mean;
    ms[g * 2 + 1] = rsqrtf(var + 1e-5f);
}

// ---------------------------------------------------------------------
// Kernel 5: normalize+swish z1, then z2 = W2 * h1 + b2.
// One block of 256 threads per (m, b). W2 (128x64 = 32 KB) in shared.
// sH stride 65 (odd) -> conflict-free across k lanes.
// ---------------------------------------------------------------------
__global__ void mlp2_kernel(const float* __restrict__ W2,
                            const float* __restrict__ b2,
                            const float* __restrict__ g1,
                            const float* __restrict__ be1) {
    const int m = blockIdx.x, b = blockIdx.y, tid = threadIdx.x;
    __shared__ float sW[C2_ * C1_];  // 32 KB
    __shared__ float sH[K_ * 65];    // 8.3 KB

    for (int i = tid; i < C2_ * C1_; i += 256) sW[i] = W2[i];
    for (int i = tid; i < C1_ * K_; i += 256) {
        int c = i >> 5, k = i & 31;
        float v = g_z1[((b * C1_ + c) * M_ + m) * K_ + k];
        int g = c >> 3;
        float mean = g_ms1[(b * G_ + g) * 2];
        float rstd = g_ms1[(b * G_ + g) * 2 + 1];
        float t = __fmul_rn(__fsub_rn(v, mean), rstd);
        t = fmaf(t, g1[c], be1[c]);
        float sgm = 1.0f / (1.0f + expf(-t));
        sH[k * 65 + c] = t * sgm;   // swish
    }
    __syncthreads();

    const int k  = tid & 31;
    const int ob = (tid >> 5) * 16;
    float acc[16];
#pragma unroll
    for (int o = 0; o < 16; o++) acc[o] = b2[ob + o];
    for (int c = 0; c < C1_; c++) {
        float f = sH[k * 65 + c];
#pragma unroll
        for (int o = 0; o < 16; o++)
            acc[o] = fmaf(sW[(ob + o) * C1_ + c], f, acc[o]);
    }
#pragma unroll
    for (int o = 0; o < 16; o++)
        g_z2[((b * C2_ + ob + o) * M_ + m) * K_ + k] = acc[o];
}

// ---------------------------------------------------------------------
// Kernel 7: normalize+swish z2, max over K -> out1 [B, C2, M].
// Swish is non-monotonic, so the activation must precede the max.
// One thread per output element; 32 contiguous floats per thread.
// ---------------------------------------------------------------------
__global__ void out_kernel(const float* __restrict__ g2,
                           const float* __restrict__ be2,
                           float* __restrict__ out) {
    const int idx = blockIdx.x * blockDim.x + threadIdx.x; // B*C2*M
    const int o = (idx >> 10) & (C2_ - 1);
    const int b = idx >> 17;
    const int g = o >> 4;
    const float mean = g_ms2[(b * G_ + g) * 2];
    const float rstd = g_ms2[(b * G_ + g) * 2 + 1];
    const float gam = g2[o], bet = be2[o];
    const float4* p = (const float4*)(g_z2 + (size_t)idx * K_);
    float mx = -3.402823466e38f;
#pragma unroll
    for (int j = 0; j < K_ / 4; j++) {
        float4 v = p[j];
        float vv[4] = {v.x, v.y, v.z, v.w};
#pragma unroll
        for (int q = 0; q < 4; q++) {
            float t = fmaf(__fmul_rn(__fsub_rn(vv[q], mean), rstd), gam, bet);
            float s = t / (1.0f + expf(-t));
            mx = fmaxf(mx, s);
        }
    }
    out[idx] = mx;
}

// ---------------------------------------------------------------------
extern "C" void kernel_launch(void* const* d_in, const int* in_sizes, int n_in,
                              void* d_out, int out_size) {
    const float* features = (const float*)d_in[0];
    const float* coords   = (const float*)d_in[1];
    const float* temb     = (const float*)d_in[2];
    const float* W1  = (const float*)d_in[3];
    const float* b1  = (const float*)d_in[4];
    const float* g1  = (const float*)d_in[5];
    const float* be1 = (const float*)d_in[6];
    const float* W2  = (const float*)d_in[7];
    const float* b2  = (const float*)d_in[8];
    const float* g2  = (const float*)d_in[9];
    const float* be2 = (const float*)d_in[10];

    float* out      = (float*)d_out;
    float* out_h    = out;                              // [B, C2, M]
    float* out_ctr  = out + B_ * C2_ * M_;              // [B, 3, M]
    float* out_temb = out_ctr + B_ * 3 * M_;            // [B, CT, M]

    fps_kernel<<<B_, 1024>>>(coords, out_ctr);
    knn_kernel<<<dim3(M_, B_), 256>>>(coords, out_ctr);
    mlp1_kernel<<<dim3(M_, B_), 256>>>(features, coords, temb, W1, b1,
                                       out_ctr, out_temb);
    gn_partial_kernel<0><<<B_ * G_ * 8, 256>>>();
    gn_finalize_kernel<0><<<1, 64>>>();
    mlp2_kernel<<<dim3(M_, B_), 256>>>(W2, b2, g1, be1);
    gn_partial_kernel<1><<<B_ * G_ * 16, 256>>>();
    gn_finalize_kernel<1><<<1, 64>>>();
    out_kernel<<<(B_ * C2_ * M_) / 256, 256>>>(g2, be2, out_h);
}